// round 10
// baseline (speedup 1.0000x reference)
#include <cuda_runtime.h>
#include <cuda_bf16.h>
#include <math.h>
#include <stdint.h>

#define TB 256
#define TT 200
#define TV 16
#define TN 64
#define TG 1024   // V*N
#define TK 1040   // V*(N+1)
#define NCTA 64
#define RTHREADS 512

__device__ float g_xT[TT][TV][TB];
__device__ float g_hsT[TT][TG][TB];
__device__ float g_aunT[TT][TV][TB];
__device__ float g_inv[TV][TB];
__device__ float g_gT[TG][TB];
__device__ __align__(16) uint32_t g_hA_hi[64 * 16 * 32 * 4];   // A fragments (h) hi
__device__ __align__(16) uint32_t g_hA_lo[64 * 16 * 32 * 4];   // A fragments (h) lo
__device__ __align__(16) uint32_t g_WB_hi[64 * 384 * 32 * 2];  // B fragments (W) hi
__device__ __align__(16) uint32_t g_WB_lo[64 * 384 * 32 * 2];  // B fragments (W) lo
__device__ unsigned g_bar;

__device__ __forceinline__ void mma_bf16(float* d, const uint32_t* a, const uint32_t* b) {
    asm volatile(
        "mma.sync.aligned.m16n8k16.row.col.f32.bf16.bf16.f32 "
        "{%0,%1,%2,%3}, {%4,%5,%6,%7}, {%8,%9}, {%0,%1,%2,%3};"
        : "+f"(d[0]), "+f"(d[1]), "+f"(d[2]), "+f"(d[3])
        : "r"(a[0]), "r"(a[1]), "r"(a[2]), "r"(a[3]), "r"(b[0]), "r"(b[1]));
}

__device__ __forceinline__ uint32_t pack_bf(float v0, float v1) {
    __nv_bfloat162 t = { __float2bfloat16(v0), __float2bfloat16(v1) };
    return *reinterpret_cast<uint32_t*>(&t);
}

__global__ void k_xT(const float* __restrict__ x) {
    int t = blockIdx.x >> 4, v = blockIdx.x & 15, b = threadIdx.x;
    g_xT[t][v][b] = x[(size_t)b * (TT * TV) + t * TV + v];
    if (blockIdx.x == 0 && threadIdx.x == 0) g_bar = 0u;
}

// precompute bf16 hi/lo B fragments of gate weights (h-part cols 16..1039)
__global__ void k_wfrag(const float* __restrict__ Wi, const float* __restrict__ Wf,
                        const float* __restrict__ Wo) {
    int nt = blockIdx.x, kc = blockIdx.y;
    int l = threadIdx.x & 31, reg = threadIdx.x >> 5;
    int n = nt * 8 + (l >> 2);
    int gate = n >> 10, u = n & 1023;
    const float* W = (gate == 0) ? Wi : (gate == 1) ? Wf : Wo;
    int k0 = kc * 16 + (l & 3) * 2 + reg * 8;
    float v0 = W[(size_t)u * TK + 16 + k0];
    float v1 = W[(size_t)u * TK + 16 + k0 + 1];
    __nv_bfloat16 h0 = __float2bfloat16(v0), h1 = __float2bfloat16(v1);
    float r0 = v0 - __bfloat162float(h0), r1 = v1 - __bfloat162float(h1);
    __nv_bfloat162 ph = { h0, h1 };
    size_t idx = ((size_t)(kc * 384 + nt) * 32 + l) * 2 + reg;
    g_WB_hi[idx] = *reinterpret_cast<uint32_t*>(&ph);
    g_WB_lo[idx] = pack_bf(r0, r1);
}

__global__ void __launch_bounds__(RTHREADS, 1) k_recur(
    const float* __restrict__ U_j, const float* __restrict__ W_j, const float* __restrict__ b_j,
    const float* __restrict__ Wi, const float* __restrict__ bi,
    const float* __restrict__ Wf, const float* __restrict__ bf,
    const float* __restrict__ Wo, const float* __restrict__ bo)
{
    __shared__ float s_wgx[16 * 48];   // x-part weights [k][r], r = g*16+u
    __shared__ float s_wj[64 * 16];    // [m][u]
    __shared__ float s_bg[48];
    __shared__ float s_bj[16];
    __shared__ float s_uu[16];
    extern __shared__ uint32_t smdyn[];
    uint32_t* s_Bh = smdyn;                     // [6 gj][64 kc][32 l][2 reg] = 24576 u32
    float*    s_D  = (float*)(smdyn + 24576);   // [48 n][256 m]

    const int tid = threadIdx.x, cta = blockIdx.x;
    const int lane = tid & 31, wid = tid >> 5;   // 16 warps
    const int g0 = cta * 16, v = g0 >> 6, n0 = g0 & 63;
    const int b = tid & 255, uh = tid >> 8;      // epilogue: batch col, unit half

    // ---- one-time staging ----
    for (int e = tid; e < 16 * 48; e += RTHREADS) {
        int k = e / 48, r = e - k * 48, g = r >> 4, u = r & 15;
        const float* W = (g == 0) ? Wi : (g == 1) ? Wf : Wo;
        s_wgx[e] = W[(size_t)(g0 + u) * TK + k];
    }
    for (int e = tid; e < 1024; e += RTHREADS)
        s_wj[e] = W_j[v * TN * TN + (e >> 4) * TN + (n0 + (e & 15))];
    if (tid < 48) {
        int g = tid >> 4, u = tid & 15;
        s_bg[tid] = ((g == 0) ? bi : (g == 1) ? bf : bo)[g0 + u];
    }
    if (tid < 16) { s_bj[tid] = b_j[v * TN + n0 + tid]; s_uu[tid] = U_j[v * TN + n0 + tid]; }
    // B-hi fragments for this CTA's 48 N-rows (6 n-tiles): nt = g*128 + cta*2 + j
    for (int e = tid; e < 24576; e += RTHREADS) {
        int reg = e & 1, l = (e >> 1) & 31, kc = (e >> 6) & 63, gj = e >> 12;
        int g = gj >> 1, j = gj & 1;
        s_Bh[e] = g_WB_hi[((size_t)(kc * 384 + g * 128 + cta * 2 + j) * 32 + l) * 2 + reg];
    }
    __syncthreads();

    // epilogue A-fragment write constants (thread = batch column b)
    const int mt_e = b >> 4, r_e = b & 15;
    const int reg_e = ((r_e >> 3) & 1) | (uh << 1);
    const int lane_e = (r_e & 7) * 4;

    float cc[8];
    #pragma unroll
    for (int u = 0; u < 8; ++u) cc[u] = 0.f;

    for (int t = 0; t < TT; ++t) {
        // ========== GEMM: M=256 (warp = m-tile) x N=48, K=1024 ==========
        if (t > 0) {
            float acc[6][4];
            #pragma unroll
            for (int gj = 0; gj < 6; ++gj)
                #pragma unroll
                for (int q = 0; q < 4; ++q) acc[gj][q] = 0.f;

            const uint4* __restrict__ Ah = (const uint4*)g_hA_hi;
            const uint4* __restrict__ Al = (const uint4*)g_hA_lo;
            const uint2* __restrict__ Bl = (const uint2*)g_WB_lo;

            uint4 ah = Ah[(0 * 16 + wid) * 32 + lane];
            uint4 al = Al[(0 * 16 + wid) * 32 + lane];
            uint2 bl2[6];
            #pragma unroll
            for (int gj = 0; gj < 6; ++gj)
                bl2[gj] = Bl[(size_t)(0 * 384 + (gj >> 1) * 128 + cta * 2 + (gj & 1)) * 32 + lane];

            #pragma unroll 4
            for (int kc = 0; kc < 64; ++kc) {
                uint4 nah, nal;
                uint2 nbl[6];
                if (kc < 63) {
                    int kn = kc + 1;
                    nah = Ah[(kn * 16 + wid) * 32 + lane];
                    nal = Al[(kn * 16 + wid) * 32 + lane];
                    #pragma unroll
                    for (int gj = 0; gj < 6; ++gj)
                        nbl[gj] = Bl[(size_t)(kn * 384 + (gj >> 1) * 128 + cta * 2 + (gj & 1)) * 32 + lane];
                }
                #pragma unroll
                for (int gj = 0; gj < 6; ++gj) {
                    uint2 bh = *(const uint2*)&s_Bh[(gj * 64 + kc) * 64 + lane * 2];
                    mma_bf16(acc[gj], (const uint32_t*)&ah, (const uint32_t*)&bh);
                    mma_bf16(acc[gj], (const uint32_t*)&al, (const uint32_t*)&bh);
                    mma_bf16(acc[gj], (const uint32_t*)&ah, (const uint32_t*)&bl2[gj]);
                }
                if (kc < 63) {
                    ah = nah; al = nal;
                    #pragma unroll
                    for (int gj = 0; gj < 6; ++gj) bl2[gj] = nbl[gj];
                }
            }
            // D -> smem transpose tile [n=48][m=256]
            int m = wid * 16 + (lane >> 2);
            #pragma unroll
            for (int gj = 0; gj < 6; ++gj) {
                int n = (gj >> 1) * 16 + (gj & 1) * 8 + (lane & 3) * 2;
                s_D[n * 256 + m]           = acc[gj][0];
                s_D[(n + 1) * 256 + m]     = acc[gj][1];
                s_D[n * 256 + m + 8]       = acc[gj][2];
                s_D[(n + 1) * 256 + m + 8] = acc[gj][3];
            }
        }
        __syncthreads();

        // ========== epilogue (thread = batch b, units g0+uh*8 .. +7) ==========
        {
            float zz[24];
            #pragma unroll
            for (int g = 0; g < 3; ++g)
                #pragma unroll
                for (int ul = 0; ul < 8; ++ul) {
                    int r = g * 16 + uh * 8 + ul;
                    zz[g * 8 + ul] = s_bg[r] + ((t > 0) ? s_D[r * 256 + b] : 0.f);
                }
            const float* xt = &g_xT[t][0][0];
            #pragma unroll
            for (int k = 0; k < TV; ++k) {
                float xv = xt[k * TB + b];
                const float* wr = s_wgx + k * 48 + uh * 8;
                #pragma unroll
                for (int g = 0; g < 3; ++g)
                    #pragma unroll
                    for (int ul = 0; ul < 8; ++ul)
                        zz[g * 8 + ul] += xv * wr[g * 16 + ul];
            }
            float xvo = xt[v * TB + b];
            float jac[8];
            #pragma unroll
            for (int ul = 0; ul < 8; ++ul)
                jac[ul] = s_bj[uh * 8 + ul] + xvo * s_uu[uh * 8 + ul];
            if (t > 0) {
                const float* hv = &g_hsT[t - 1][v * TN][0];
                #pragma unroll 8
                for (int m = 0; m < TN; ++m) {
                    float hm = hv[m * TB + b];
                    const float* wr = s_wj + m * 16 + uh * 8;
                    #pragma unroll
                    for (int ul = 0; ul < 8; ++ul) jac[ul] += hm * wr[ul];
                }
            }
            float hval[8];
            float* ho = &g_hsT[t][0][0];
            #pragma unroll
            for (int ul = 0; ul < 8; ++ul) {
                float iv = 1.f / (1.f + expf(-zz[ul]));
                float fv = 1.f / (1.f + expf(-zz[8 + ul]));
                float ov = 1.f / (1.f + expf(-zz[16 + ul]));
                float jv = tanhf(jac[ul]);
                float cn = cc[ul] * fv + iv * jv;
                cc[ul] = cn;
                hval[ul] = ov * tanhf(cn);
                ho[(size_t)(g0 + uh * 8 + ul) * TB + b] = hval[ul];
            }
            // A fragments: kc = cta (16 units per CTA = one kc block)
            #pragma unroll
            for (int p = 0; p < 4; ++p) {
                float v0 = hval[2 * p], v1 = hval[2 * p + 1];
                __nv_bfloat16 h0 = __float2bfloat16(v0), h1 = __float2bfloat16(v1);
                float q0 = v0 - __bfloat162float(h0), q1 = v1 - __bfloat162float(h1);
                __nv_bfloat162 ph = { h0, h1 };
                size_t idx = ((size_t)(cta * 16 + mt_e) * 32 + lane_e + p) * 4 + reg_e;
                g_hA_hi[idx] = *reinterpret_cast<uint32_t*>(&ph);
                g_hA_lo[idx] = pack_bf(q0, q1);
            }
        }

        // single grid barrier per step (h + fragments ready)
        __syncthreads();
        if (tid == 0) {
            __threadfence(); atomicAdd(&g_bar, 1u);
            unsigned target = (unsigned)(t + 1) * NCTA;
            while (*((volatile unsigned*)&g_bar) < target) { }
            __threadfence();
        }
        __syncthreads();
    }
}

__global__ void k_alphaA(const float* __restrict__ Fa, const float* __restrict__ Fab) {
    __shared__ float fa[TN]; __shared__ float fabv;
    int v = blockIdx.x, t0 = blockIdx.y * 8, b = threadIdx.x;
    if (threadIdx.x < TN) fa[threadIdx.x] = Fa[v * TN + threadIdx.x];
    if (threadIdx.x == 0) fabv = Fab[v];
    __syncthreads();
    for (int t = t0; t < t0 + 8; ++t) {
        const float* hr = &g_hsT[t][v * TN][0];
        float ap = fabv;
        #pragma unroll 8
        for (int n = 0; n < TN; ++n) ap += hr[n * TB + b] * fa[n];
        g_aunT[t][v][b] = expf(tanhf(ap));
    }
}

__global__ void k_alphaInv() {
    int v = blockIdx.x, b = threadIdx.x;
    float s = 0.f;
    for (int t = 0; t < TT; ++t) s += g_aunT[t][v][b];
    g_inv[v][b] = 1.f / s;
}

__global__ void k_gn() {
    int v = blockIdx.x, nc = blockIdx.y * 2, b = threadIdx.x;
    float a0 = 0.f, a1 = 0.f;
    for (int t = 0; t < TT; ++t) {
        float au = g_aunT[t][v][b];
        const float* hr = &g_hsT[t][v * TN + nc][0];
        a0 += au * hr[0 * TB + b];
        a1 += au * hr[1 * TB + b];
    }
    float inv = g_inv[v][b];
    g_gT[v * TN + nc + 0][b] = a0 * inv;
    g_gT[v * TN + nc + 1][b] = a1 * inv;
}

__global__ void k_alphaOut(float* __restrict__ out) {
    int t = blockIdx.x, b = threadIdx.x;
    float* ao = out + TB;
    #pragma unroll
    for (int v = 0; v < TV; ++v)
        ao[((size_t)b * TT + t) * TV + v] = g_aunT[t][v][b] * g_inv[v][b];
}

__global__ void k_final(const float* __restrict__ Fbw, const float* __restrict__ Fbb,
                        const float* __restrict__ Phw, const float* __restrict__ Phb,
                        float* __restrict__ out) {
    __shared__ float phi[2 * TN], fbw[2 * TN];
    __shared__ float phib, fbb;
    int b = threadIdx.x;
    if (threadIdx.x < 2 * TN) { phi[threadIdx.x] = Phw[threadIdx.x]; fbw[threadIdx.x] = Fbw[threadIdx.x]; }
    if (threadIdx.x == 0) { phib = Phb[0]; fbb = Fbb[0]; }
    __syncthreads();
    float mu[TV], bu[TV], bs = 0.f;
    #pragma unroll
    for (int v = 0; v < TV; ++v) {
        const float* gr = &g_gT[v * TN][0];
        const float* hr = &g_hsT[TT - 1][v * TN][0];
        float m_ = phib, p_ = fbb;
        #pragma unroll 8
        for (int n = 0; n < TN; ++n) {
            float gv = gr[n * TB + b], hv = hr[n * TB + b];
            m_ += gv * phi[n] + hv * phi[TN + n];
            p_ += gv * fbw[n] + hv * fbw[TN + n];
        }
        mu[v] = m_;
        float e = expf(tanhf(p_));
        bu[v] = e; bs += e;
    }
    float ib = 1.f / bs, mean = 0.f;
    float* bout = out + TB + (size_t)TB * TT * TV;
    #pragma unroll
    for (int v = 0; v < TV; ++v) {
        float be = bu[v] * ib;
        mean += be * mu[v];
        bout[(size_t)b * TV + v] = be;
    }
    out[b] = mean;
}

extern "C" void kernel_launch(void* const* d_in, const int* in_sizes, int n_in,
                              void* d_out, int out_size) {
    const float* x    = (const float*)d_in[0];
    const float* U_j  = (const float*)d_in[1];
    const float* W_j  = (const float*)d_in[2];
    const float* b_j  = (const float*)d_in[3];
    const float* Wi   = (const float*)d_in[4];
    const float* bi   = (const float*)d_in[5];
    const float* Wf   = (const float*)d_in[6];
    const float* bf   = (const float*)d_in[7];
    const float* Wo   = (const float*)d_in[8];
    const float* bo   = (const float*)d_in[9];
    const float* Fa   = (const float*)d_in[10];
    const float* Fab  = (const float*)d_in[11];
    const float* Fbw  = (const float*)d_in[12];
    const float* Fbb  = (const float*)d_in[13];
    const float* Phw  = (const float*)d_in[14];
    const float* Phb  = (const float*)d_in[15];
    float* out = (float*)d_out;

    static const int SMEM = 24576 * 4 + 48 * 256 * 4;  // B-hi frags + D tile = 147456 B
    cudaFuncSetAttribute(k_recur, cudaFuncAttributeMaxDynamicSharedMemorySize, SMEM);

    k_xT<<<TT * TV, TB>>>(x);
    k_wfrag<<<dim3(384, 64), 64>>>(Wi, Wf, Wo);
    k_recur<<<NCTA, RTHREADS, SMEM>>>(U_j, W_j, b_j, Wi, bi, Wf, bf, Wo, bo);
    k_alphaA<<<dim3(TV, 25), TB>>>(Fa, Fab);
    k_alphaInv<<<TV, TB>>>();
    k_gn<<<dim3(TV, 32), TB>>>();
    k_alphaOut<<<TT, TB>>>(out);
    k_final<<<1, TB>>>(Fbw, Fbb, Phw, Phb, out);
}

// round 11
// speedup vs baseline: 1.2544x; 1.2544x over previous
#include <cuda_runtime.h>
#include <cuda_bf16.h>
#include <math.h>
#include <stdint.h>

#define TB 256
#define TT 200
#define TV 16
#define TN 64
#define TG 1024   // V*N
#define TK 1040   // V*(N+1)
#define NCTA 128
#define RTHREADS 256

__device__ float g_xT[TT][TV][TB];
__device__ float g_hsT[TT][TG][TB];
__device__ float g_aunT[TT][TV][TB];
__device__ float g_inv[TV][TB];
__device__ float g_gT[TG][TB];
__device__ __align__(16) uint32_t g_hA_hi[64 * 16 * 32 * 4];   // A fragments (h) hi
__device__ __align__(16) uint32_t g_hA_lo[64 * 16 * 32 * 4];   // A fragments (h) lo
__device__ __align__(16) uint32_t g_WB_hi[64 * 384 * 32 * 2];  // B fragments (W) hi
__device__ __align__(16) uint32_t g_WB_lo[64 * 384 * 32 * 2];  // B fragments (W) lo
__device__ unsigned g_bar;

__device__ __forceinline__ void mma_bf16(float* d, const uint32_t* a, const uint32_t* b) {
    asm volatile(
        "mma.sync.aligned.m16n8k16.row.col.f32.bf16.bf16.f32 "
        "{%0,%1,%2,%3}, {%4,%5,%6,%7}, {%8,%9}, {%0,%1,%2,%3};"
        : "+f"(d[0]), "+f"(d[1]), "+f"(d[2]), "+f"(d[3])
        : "r"(a[0]), "r"(a[1]), "r"(a[2]), "r"(a[3]), "r"(b[0]), "r"(b[1]));
}

__device__ __forceinline__ uint32_t pack_bf(float v0, float v1) {
    __nv_bfloat162 t = { __float2bfloat16(v0), __float2bfloat16(v1) };
    return *reinterpret_cast<uint32_t*>(&t);
}

__global__ void k_xT(const float* __restrict__ x) {
    int t = blockIdx.x >> 4, v = blockIdx.x & 15, b = threadIdx.x;
    g_xT[t][v][b] = x[(size_t)b * (TT * TV) + t * TV + v];
    if (blockIdx.x == 0 && threadIdx.x == 0) g_bar = 0u;
}

// precompute bf16 hi/lo B fragments of gate weights (h-part cols 16..1039)
__global__ void k_wfrag(const float* __restrict__ Wi, const float* __restrict__ Wf,
                        const float* __restrict__ Wo) {
    int nt = blockIdx.x, kc = blockIdx.y;
    int l = threadIdx.x & 31, reg = threadIdx.x >> 5;
    int n = nt * 8 + (l >> 2);
    int gate = n >> 10, u = n & 1023;
    const float* W = (gate == 0) ? Wi : (gate == 1) ? Wf : Wo;
    int k0 = kc * 16 + (l & 3) * 2 + reg * 8;
    float v0 = W[(size_t)u * TK + 16 + k0];
    float v1 = W[(size_t)u * TK + 16 + k0 + 1];
    __nv_bfloat16 h0 = __float2bfloat16(v0), h1 = __float2bfloat16(v1);
    float r0 = v0 - __bfloat162float(h0), r1 = v1 - __bfloat162float(h1);
    __nv_bfloat162 ph = { h0, h1 };
    size_t idx = ((size_t)(kc * 384 + nt) * 32 + l) * 2 + reg;
    g_WB_hi[idx] = *reinterpret_cast<uint32_t*>(&ph);
    g_WB_lo[idx] = pack_bf(r0, r1);
}

__global__ void __launch_bounds__(RTHREADS, 1) k_recur(
    const float* __restrict__ U_j, const float* __restrict__ W_j, const float* __restrict__ b_j,
    const float* __restrict__ Wi, const float* __restrict__ bi,
    const float* __restrict__ Wf, const float* __restrict__ bf,
    const float* __restrict__ Wo, const float* __restrict__ bo)
{
    __shared__ float s_wgx[16 * 24];   // x-part weights [k][r], r = gate*8+ul
    __shared__ float s_wj[64 * 8];
    __shared__ float s_bg[24];
    __shared__ float s_bj[8];
    __shared__ float s_uu[8];
    extern __shared__ uint32_t smdyn[];
    uint32_t* s_Bh = smdyn;                     // [3][64][32][2] = 12288 u32
    uint32_t* s_Bl = smdyn + 12288;             // 12288 u32
    float*    s_D  = (float*)(smdyn + 24576);   // [24][256]

    const int tid = threadIdx.x, cta = blockIdx.x;
    const int lane = tid & 31, wid = tid >> 5;
    const int g0 = cta * 8, v = g0 >> 6, n0 = g0 & 63;
    const int b = tid;

    // ---- one-time staging ----
    for (int e = tid; e < 16 * 24; e += RTHREADS) {
        int k = e / 24, r = e - k * 24, g = r >> 3, ul = r & 7;
        const float* W = (g == 0) ? Wi : (g == 1) ? Wf : Wo;
        s_wgx[e] = W[(size_t)(g0 + ul) * TK + k];
    }
    for (int e = tid; e < 512; e += RTHREADS)
        s_wj[e] = W_j[v * TN * TN + (e >> 3) * TN + (n0 + (e & 7))];
    if (tid < 24) {
        int g = tid >> 3, ul = tid & 7;
        s_bg[tid] = ((g == 0) ? bi : (g == 1) ? bf : bo)[g0 + ul];
    }
    if (tid < 8) { s_bj[tid] = b_j[v * TN + n0 + tid]; s_uu[tid] = U_j[v * TN + n0 + tid]; }
    // B fragments for this CTA's 24 N-rows: nt = g*128 + cta
    for (int e = tid; e < 12288; e += RTHREADS) {
        int reg = e & 1, l = (e >> 1) & 31, kc = (e >> 6) & 63, g = e >> 12;
        size_t src = ((size_t)(kc * 384 + g * 128 + cta) * 32 + l) * 2 + reg;
        s_Bh[e] = g_WB_hi[src];
        s_Bl[e] = g_WB_lo[src];
    }
    __syncthreads();

    // epilogue A-fragment write constants (thread = batch column b)
    const int kc_e = g0 >> 4;
    const int mt_e = b >> 4, r_e = b & 15;
    const int reg_e = ((r_e >> 3) & 1) | ((g0 & 8) ? 2 : 0);
    const int lane_e = (r_e & 7) * 4;

    float cc[8];
    #pragma unroll
    for (int u = 0; u < 8; ++u) cc[u] = 0.f;

    for (int t = 0; t < TT; ++t) {
        // ========== GEMM: 24 N-rows x 256 batch, K=1024, depth-2 A prefetch ==========
        if (t > 0) {
            float acc[2][3][4];
            #pragma unroll
            for (int i = 0; i < 2; ++i)
                #pragma unroll
                for (int g = 0; g < 3; ++g)
                    #pragma unroll
                    for (int q = 0; q < 4; ++q) acc[i][g][q] = 0.f;

            const uint4* __restrict__ Ah = (const uint4*)g_hA_hi;
            const uint4* __restrict__ Al = (const uint4*)g_hA_lo;
            const int mt0 = wid * 2, mt1 = mt0 + 1;

            // pipeline buffers: a = kc, b = kc+1
            uint4 ah0a = Ah[(0 * 16 + mt0) * 32 + lane];
            uint4 ah1a = Ah[(0 * 16 + mt1) * 32 + lane];
            uint4 al0a = Al[(0 * 16 + mt0) * 32 + lane];
            uint4 al1a = Al[(0 * 16 + mt1) * 32 + lane];
            uint4 ah0b = Ah[(1 * 16 + mt0) * 32 + lane];
            uint4 ah1b = Ah[(1 * 16 + mt1) * 32 + lane];
            uint4 al0b = Al[(1 * 16 + mt0) * 32 + lane];
            uint4 al1b = Al[(1 * 16 + mt1) * 32 + lane];

            #pragma unroll 2
            for (int kc = 0; kc < 64; ++kc) {
                uint4 nh0, nh1, nl0, nl1;
                if (kc + 2 < 64) {
                    int kn = kc + 2;
                    nh0 = Ah[(kn * 16 + mt0) * 32 + lane];
                    nh1 = Ah[(kn * 16 + mt1) * 32 + lane];
                    nl0 = Al[(kn * 16 + mt0) * 32 + lane];
                    nl1 = Al[(kn * 16 + mt1) * 32 + lane];
                }
                #pragma unroll
                for (int g = 0; g < 3; ++g) {
                    uint2 bh = *(const uint2*)&s_Bh[((g * 64 + kc) * 32 + lane) * 2];
                    uint2 bl = *(const uint2*)&s_Bl[((g * 64 + kc) * 32 + lane) * 2];
                    mma_bf16(acc[0][g], (const uint32_t*)&ah0a, (const uint32_t*)&bh);
                    mma_bf16(acc[0][g], (const uint32_t*)&al0a, (const uint32_t*)&bh);
                    mma_bf16(acc[0][g], (const uint32_t*)&ah0a, (const uint32_t*)&bl);
                    mma_bf16(acc[1][g], (const uint32_t*)&ah1a, (const uint32_t*)&bh);
                    mma_bf16(acc[1][g], (const uint32_t*)&al1a, (const uint32_t*)&bh);
                    mma_bf16(acc[1][g], (const uint32_t*)&ah1a, (const uint32_t*)&bl);
                }
                ah0a = ah0b; ah1a = ah1b; al0a = al0b; al1a = al1b;
                if (kc + 2 < 64) { ah0b = nh0; ah1b = nh1; al0b = nl0; al1b = nl1; }
            }
            // D -> smem transpose tile [n=24][batch=256]
            #pragma unroll
            for (int i = 0; i < 2; ++i) {
                int mbase = (wid * 2 + i) * 16 + (lane >> 2);
                #pragma unroll
                for (int g = 0; g < 3; ++g) {
                    int n = g * 8 + (lane & 3) * 2;
                    s_D[n * TB + mbase]           = acc[i][g][0];
                    s_D[(n + 1) * TB + mbase]     = acc[i][g][1];
                    s_D[n * TB + mbase + 8]       = acc[i][g][2];
                    s_D[(n + 1) * TB + mbase + 8] = acc[i][g][3];
                }
            }
        }
        __syncthreads();

        // ========== epilogue (thread = batch b) ==========
        {
            float zz[24];
            #pragma unroll
            for (int r = 0; r < 24; ++r)
                zz[r] = s_bg[r] + ((t > 0) ? s_D[r * TB + b] : 0.f);
            const float* xt = &g_xT[t][0][0];
            #pragma unroll
            for (int k = 0; k < TV; ++k) {
                float xv = xt[k * TB + b];
                const float* wr = s_wgx + k * 24;
                #pragma unroll
                for (int r = 0; r < 24; ++r) zz[r] += xv * wr[r];
            }
            float xvo = xt[v * TB + b];
            float jac[8];
            #pragma unroll
            for (int u = 0; u < 8; ++u) jac[u] = s_bj[u] + xvo * s_uu[u];
            if (t > 0) {
                const float* hv = &g_hsT[t - 1][v * TN][0];
                #pragma unroll 8
                for (int m = 0; m < TN; ++m) {
                    float hm = hv[m * TB + b];
                    const float* wr = s_wj + m * 8;
                    #pragma unroll
                    for (int u = 0; u < 8; ++u) jac[u] += hm * wr[u];
                }
            }
            float hval[8];
            float* ho = &g_hsT[t][0][0];
            #pragma unroll
            for (int ul = 0; ul < 8; ++ul) {
                float iv = 1.f / (1.f + expf(-zz[ul]));
                float fv = 1.f / (1.f + expf(-zz[8 + ul]));
                float ov = 1.f / (1.f + expf(-zz[16 + ul]));
                float jv = tanhf(jac[ul]);
                float cn = cc[ul] * fv + iv * jv;
                cc[ul] = cn;
                hval[ul] = ov * tanhf(cn);
                ho[(size_t)(g0 + ul) * TB + b] = hval[ul];
            }
            #pragma unroll
            for (int p = 0; p < 4; ++p) {
                float v0 = hval[2 * p], v1 = hval[2 * p + 1];
                __nv_bfloat16 h0 = __float2bfloat16(v0), h1 = __float2bfloat16(v1);
                float q0 = v0 - __bfloat162float(h0), q1 = v1 - __bfloat162float(h1);
                __nv_bfloat162 ph = { h0, h1 };
                size_t idx = ((size_t)(kc_e * 16 + mt_e) * 32 + lane_e + p) * 4 + reg_e;
                g_hA_hi[idx] = *reinterpret_cast<uint32_t*>(&ph);
                g_hA_lo[idx] = pack_bf(q0, q1);
            }
        }

        // single grid barrier per step (h + fragments ready)
        __syncthreads();
        if (tid == 0) {
            __threadfence(); atomicAdd(&g_bar, 1u);
            unsigned target = (unsigned)(t + 1) * NCTA;
            while (*((volatile unsigned*)&g_bar) < target) { }
            __threadfence();
        }
        __syncthreads();
    }
}

__global__ void k_alphaA(const float* __restrict__ Fa, const float* __restrict__ Fab) {
    __shared__ float fa[TN]; __shared__ float fabv;
    int v = blockIdx.x, t0 = blockIdx.y * 8, b = threadIdx.x;
    if (threadIdx.x < TN) fa[threadIdx.x] = Fa[v * TN + threadIdx.x];
    if (threadIdx.x == 0) fabv = Fab[v];
    __syncthreads();
    for (int t = t0; t < t0 + 8; ++t) {
        const float* hr = &g_hsT[t][v * TN][0];
        float ap = fabv;
        #pragma unroll 8
        for (int n = 0; n < TN; ++n) ap += hr[n * TB + b] * fa[n];
        g_aunT[t][v][b] = expf(tanhf(ap));
    }
}

__global__ void k_alphaInv() {
    int v = blockIdx.x, b = threadIdx.x;
    float s = 0.f;
    for (int t = 0; t < TT; ++t) s += g_aunT[t][v][b];
    g_inv[v][b] = 1.f / s;
}

__global__ void k_gn() {
    int v = blockIdx.x, nc = blockIdx.y * 2, b = threadIdx.x;
    float a0 = 0.f, a1 = 0.f;
    for (int t = 0; t < TT; ++t) {
        float au = g_aunT[t][v][b];
        const float* hr = &g_hsT[t][v * TN + nc][0];
        a0 += au * hr[0 * TB + b];
        a1 += au * hr[1 * TB + b];
    }
    float inv = g_inv[v][b];
    g_gT[v * TN + nc + 0][b] = a0 * inv;
    g_gT[v * TN + nc + 1][b] = a1 * inv;
}

__global__ void k_alphaOut(float* __restrict__ out) {
    int t = blockIdx.x, b = threadIdx.x;
    float* ao = out + TB;
    #pragma unroll
    for (int v = 0; v < TV; ++v)
        ao[((size_t)b * TT + t) * TV + v] = g_aunT[t][v][b] * g_inv[v][b];
}

__global__ void k_final(const float* __restrict__ Fbw, const float* __restrict__ Fbb,
                        const float* __restrict__ Phw, const float* __restrict__ Phb,
                        float* __restrict__ out) {
    __shared__ float phi[2 * TN], fbw[2 * TN];
    __shared__ float phib, fbb;
    int b = threadIdx.x;
    if (threadIdx.x < 2 * TN) { phi[threadIdx.x] = Phw[threadIdx.x]; fbw[threadIdx.x] = Fbw[threadIdx.x]; }
    if (threadIdx.x == 0) { phib = Phb[0]; fbb = Fbb[0]; }
    __syncthreads();
    float mu[TV], bu[TV], bs = 0.f;
    #pragma unroll
    for (int v = 0; v < TV; ++v) {
        const float* gr = &g_gT[v * TN][0];
        const float* hr = &g_hsT[TT - 1][v * TN][0];
        float m_ = phib, p_ = fbb;
        #pragma unroll 8
        for (int n = 0; n < TN; ++n) {
            float gv = gr[n * TB + b], hv = hr[n * TB + b];
            m_ += gv * phi[n] + hv * phi[TN + n];
            p_ += gv * fbw[n] + hv * fbw[TN + n];
        }
        mu[v] = m_;
        float e = expf(tanhf(p_));
        bu[v] = e; bs += e;
    }
    float ib = 1.f / bs, mean = 0.f;
    float* bout = out + TB + (size_t)TB * TT * TV;
    #pragma unroll
    for (int v = 0; v < TV; ++v) {
        float be = bu[v] * ib;
        mean += be * mu[v];
        bout[(size_t)b * TV + v] = be;
    }
    out[b] = mean;
}

extern "C" void kernel_launch(void* const* d_in, const int* in_sizes, int n_in,
                              void* d_out, int out_size) {
    const float* x    = (const float*)d_in[0];
    const float* U_j  = (const float*)d_in[1];
    const float* W_j  = (const float*)d_in[2];
    const float* b_j  = (const float*)d_in[3];
    const float* Wi   = (const float*)d_in[4];
    const float* bi   = (const float*)d_in[5];
    const float* Wf   = (const float*)d_in[6];
    const float* bf   = (const float*)d_in[7];
    const float* Wo   = (const float*)d_in[8];
    const float* bo   = (const float*)d_in[9];
    const float* Fa   = (const float*)d_in[10];
    const float* Fab  = (const float*)d_in[11];
    const float* Fbw  = (const float*)d_in[12];
    const float* Fbb  = (const float*)d_in[13];
    const float* Phw  = (const float*)d_in[14];
    const float* Phb  = (const float*)d_in[15];
    float* out = (float*)d_out;

    static const int SMEM = 24576 * 4 + 24 * TB * 4;  // B frags + D tile = 122880 B
    cudaFuncSetAttribute(k_recur, cudaFuncAttributeMaxDynamicSharedMemorySize, SMEM);

    k_xT<<<TT * TV, TB>>>(x);
    k_wfrag<<<dim3(384, 64), 64>>>(Wi, Wf, Wo);
    k_recur<<<NCTA, RTHREADS, SMEM>>>(U_j, W_j, b_j, Wi, bi, Wf, bf, Wo, bo);
    k_alphaA<<<dim3(TV, 25), TB>>>(Fa, Fab);
    k_alphaInv<<<TV, TB>>>();
    k_gn<<<dim3(TV, 32), TB>>>();
    k_alphaOut<<<TT, TB>>>(out);
    k_final<<<1, TB>>>(Fbw, Fbb, Phw, Phb, out);
}

// round 12
// speedup vs baseline: 1.7979x; 1.4332x over previous
#include <cuda_runtime.h>
#include <cuda_bf16.h>
#include <math.h>
#include <stdint.h>

#define TB 256
#define TT 200
#define TV 16
#define TN 64
#define TG 1024   // V*N
#define TK 1040   // V*(N+1)
#define NCTA 128
#define RTHREADS 256

__device__ float g_xT[TT][TV][TB];
__device__ float g_hsT[TT][TG][TB];
__device__ float g_aunT[TT][TV][TB];
__device__ float g_inv[TV][TB];
__device__ float g_gT[TG][TB];
__device__ __align__(16) uint32_t g_hA_hi[64 * 16 * 32 * 4];   // A fragments (h) hi
__device__ __align__(16) uint32_t g_hA_lo[64 * 16 * 32 * 4];   // A fragments (h) lo
__device__ __align__(16) uint32_t g_WB_hi[64 * 384 * 32 * 2];  // B fragments (W) hi
__device__ unsigned g_bar;

__device__ __forceinline__ void mma_bf16(float* d, const uint32_t* a, const uint32_t* b) {
    asm volatile(
        "mma.sync.aligned.m16n8k16.row.col.f32.bf16.bf16.f32 "
        "{%0,%1,%2,%3}, {%4,%5,%6,%7}, {%8,%9}, {%0,%1,%2,%3};"
        : "+f"(d[0]), "+f"(d[1]), "+f"(d[2]), "+f"(d[3])
        : "r"(a[0]), "r"(a[1]), "r"(a[2]), "r"(a[3]), "r"(b[0]), "r"(b[1]));
}

__device__ __forceinline__ uint32_t pack_bf(float v0, float v1) {
    __nv_bfloat162 t = { __float2bfloat16(v0), __float2bfloat16(v1) };
    return *reinterpret_cast<uint32_t*>(&t);
}

__global__ void k_xT(const float* __restrict__ x) {
    int t = blockIdx.x >> 4, v = blockIdx.x & 15, b = threadIdx.x;
    g_xT[t][v][b] = x[(size_t)b * (TT * TV) + t * TV + v];
    if (blockIdx.x == 0 && threadIdx.x == 0) g_bar = 0u;
}

// precompute bf16 B fragments of gate weights (h-part cols 16..1039)
__global__ void k_wfrag(const float* __restrict__ Wi, const float* __restrict__ Wf,
                        const float* __restrict__ Wo) {
    int nt = blockIdx.x, kc = blockIdx.y;
    int l = threadIdx.x & 31, reg = threadIdx.x >> 5;
    int n = nt * 8 + (l >> 2);
    int gate = n >> 10, u = n & 1023;
    const float* W = (gate == 0) ? Wi : (gate == 1) ? Wf : Wo;
    int k0 = kc * 16 + (l & 3) * 2 + reg * 8;
    float v0 = W[(size_t)u * TK + 16 + k0];
    float v1 = W[(size_t)u * TK + 16 + k0 + 1];
    g_WB_hi[((size_t)(kc * 384 + nt) * 32 + l) * 2 + reg] = pack_bf(v0, v1);
}

__global__ void __launch_bounds__(RTHREADS, 1) k_recur(
    const float* __restrict__ U_j, const float* __restrict__ W_j, const float* __restrict__ b_j,
    const float* __restrict__ Wi, const float* __restrict__ bi,
    const float* __restrict__ Wf, const float* __restrict__ bf,
    const float* __restrict__ Wo, const float* __restrict__ bo)
{
    __shared__ float s_wgx[16 * 24];   // x-part weights [k][r], r = gate*8+ul
    __shared__ float s_wj[64 * 8];
    __shared__ float s_bg[24];
    __shared__ float s_bj[8];
    __shared__ float s_uu[8];
    extern __shared__ uint32_t smdyn[];
    uint32_t* s_Bh = smdyn;                     // [3][64][32][2] = 12288 u32
    float*    s_D  = (float*)(smdyn + 12288);   // [24][256]

    const int tid = threadIdx.x, cta = blockIdx.x;
    const int lane = tid & 31, wid = tid >> 5;
    const int g0 = cta * 8, v = g0 >> 6, n0 = g0 & 63;
    const int b = tid;

    // ---- one-time staging ----
    for (int e = tid; e < 16 * 24; e += RTHREADS) {
        int k = e / 24, r = e - k * 24, g = r >> 3, ul = r & 7;
        const float* W = (g == 0) ? Wi : (g == 1) ? Wf : Wo;
        s_wgx[e] = W[(size_t)(g0 + ul) * TK + k];
    }
    for (int e = tid; e < 512; e += RTHREADS)
        s_wj[e] = W_j[v * TN * TN + (e >> 3) * TN + (n0 + (e & 7))];
    if (tid < 24) {
        int g = tid >> 3, ul = tid & 7;
        s_bg[tid] = ((g == 0) ? bi : (g == 1) ? bf : bo)[g0 + ul];
    }
    if (tid < 8) { s_bj[tid] = b_j[v * TN + n0 + tid]; s_uu[tid] = U_j[v * TN + n0 + tid]; }
    // B fragments for this CTA's 24 N-rows: nt = g*128 + cta
    for (int e = tid; e < 12288; e += RTHREADS) {
        int reg = e & 1, l = (e >> 1) & 31, kc = (e >> 6) & 63, g = e >> 12;
        s_Bh[e] = g_WB_hi[((size_t)(kc * 384 + g * 128 + cta) * 32 + l) * 2 + reg];
    }
    __syncthreads();

    // epilogue A-fragment write constants (thread = batch column b)
    const int kc_e = g0 >> 4;
    const int mt_e = b >> 4, r_e = b & 15;
    const int reg_e = ((r_e >> 3) & 1) | ((g0 & 8) ? 2 : 0);
    const int lane_e = (r_e & 7) * 4;

    float cc[8];
    #pragma unroll
    for (int u = 0; u < 8; ++u) cc[u] = 0.f;

    for (int t = 0; t < TT; ++t) {
        // ========== GEMM: 24 N-rows x 256 batch, K=1024, 2-term bf16 ==========
        if (t > 0) {
            float acc[2][3][4];
            #pragma unroll
            for (int i = 0; i < 2; ++i)
                #pragma unroll
                for (int g = 0; g < 3; ++g)
                    #pragma unroll
                    for (int q = 0; q < 4; ++q) acc[i][g][q] = 0.f;

            const uint4* __restrict__ Ah = (const uint4*)g_hA_hi;
            const uint4* __restrict__ Al = (const uint4*)g_hA_lo;
            const int mt0 = wid * 2, mt1 = mt0 + 1;

            uint4 ah0 = Ah[(0 * 16 + mt0) * 32 + lane];
            uint4 ah1 = Ah[(0 * 16 + mt1) * 32 + lane];
            uint4 al0 = Al[(0 * 16 + mt0) * 32 + lane];
            uint4 al1 = Al[(0 * 16 + mt1) * 32 + lane];

            #pragma unroll 4
            for (int kc = 0; kc < 64; ++kc) {
                uint4 nah0, nah1, nal0, nal1;
                if (kc < 63) {
                    int kn = kc + 1;
                    nah0 = Ah[(kn * 16 + mt0) * 32 + lane];
                    nah1 = Ah[(kn * 16 + mt1) * 32 + lane];
                    nal0 = Al[(kn * 16 + mt0) * 32 + lane];
                    nal1 = Al[(kn * 16 + mt1) * 32 + lane];
                }
                #pragma unroll
                for (int g = 0; g < 3; ++g) {
                    uint2 bh = *(const uint2*)&s_Bh[((g * 64 + kc) * 32 + lane) * 2];
                    mma_bf16(acc[0][g], (const uint32_t*)&ah0, (const uint32_t*)&bh);
                    mma_bf16(acc[0][g], (const uint32_t*)&al0, (const uint32_t*)&bh);
                    mma_bf16(acc[1][g], (const uint32_t*)&ah1, (const uint32_t*)&bh);
                    mma_bf16(acc[1][g], (const uint32_t*)&al1, (const uint32_t*)&bh);
                }
                if (kc < 63) { ah0 = nah0; ah1 = nah1; al0 = nal0; al1 = nal1; }
            }
            // D -> smem transpose tile [n=24][batch=256]
            #pragma unroll
            for (int i = 0; i < 2; ++i) {
                int mbase = (wid * 2 + i) * 16 + (lane >> 2);
                #pragma unroll
                for (int g = 0; g < 3; ++g) {
                    int n = g * 8 + (lane & 3) * 2;
                    s_D[n * TB + mbase]           = acc[i][g][0];
                    s_D[(n + 1) * TB + mbase]     = acc[i][g][1];
                    s_D[n * TB + mbase + 8]       = acc[i][g][2];
                    s_D[(n + 1) * TB + mbase + 8] = acc[i][g][3];
                }
            }
        }
        __syncthreads();

        // ========== epilogue (thread = batch b) ==========
        {
            float zz[24];
            #pragma unroll
            for (int r = 0; r < 24; ++r)
                zz[r] = s_bg[r] + ((t > 0) ? s_D[r * TB + b] : 0.f);
            const float* xt = &g_xT[t][0][0];
            #pragma unroll
            for (int k = 0; k < TV; ++k) {
                float xv = xt[k * TB + b];
                const float* wr = s_wgx + k * 24;
                #pragma unroll
                for (int r = 0; r < 24; ++r) zz[r] += xv * wr[r];
            }
            float xvo = xt[v * TB + b];
            float jac[8];
            #pragma unroll
            for (int u = 0; u < 8; ++u) jac[u] = s_bj[u] + xvo * s_uu[u];
            if (t > 0) {
                const float* hv = &g_hsT[t - 1][v * TN][0];
                #pragma unroll 8
                for (int m = 0; m < TN; ++m) {
                    float hm = hv[m * TB + b];
                    const float* wr = s_wj + m * 8;
                    #pragma unroll
                    for (int u = 0; u < 8; ++u) jac[u] += hm * wr[u];
                }
            }
            float hval[8];
            float* ho = &g_hsT[t][0][0];
            #pragma unroll
            for (int ul = 0; ul < 8; ++ul) {
                float iv = 1.f / (1.f + expf(-zz[ul]));
                float fv = 1.f / (1.f + expf(-zz[8 + ul]));
                float ov = 1.f / (1.f + expf(-zz[16 + ul]));
                float jv = tanhf(jac[ul]);
                float cn = cc[ul] * fv + iv * jv;
                cc[ul] = cn;
                hval[ul] = ov * tanhf(cn);
                ho[(size_t)(g0 + ul) * TB + b] = hval[ul];
            }
            #pragma unroll
            for (int p = 0; p < 4; ++p) {
                float v0 = hval[2 * p], v1 = hval[2 * p + 1];
                __nv_bfloat16 h0 = __float2bfloat16(v0), h1 = __float2bfloat16(v1);
                float q0 = v0 - __bfloat162float(h0), q1 = v1 - __bfloat162float(h1);
                __nv_bfloat162 ph = { h0, h1 };
                size_t idx = ((size_t)(kc_e * 16 + mt_e) * 32 + lane_e + p) * 4 + reg_e;
                g_hA_hi[idx] = *reinterpret_cast<uint32_t*>(&ph);
                g_hA_lo[idx] = pack_bf(q0, q1);
            }
        }

        // single grid barrier per step (h + fragments ready)
        __syncthreads();
        if (tid == 0) {
            __threadfence(); atomicAdd(&g_bar, 1u);
            unsigned target = (unsigned)(t + 1) * NCTA;
            while (*((volatile unsigned*)&g_bar) < target) { }
            __threadfence();
        }
        __syncthreads();
    }
}

__global__ void k_alphaA(const float* __restrict__ Fa, const float* __restrict__ Fab) {
    __shared__ float fa[TN]; __shared__ float fabv;
    int v = blockIdx.x, t0 = blockIdx.y * 8, b = threadIdx.x;
    if (threadIdx.x < TN) fa[threadIdx.x] = Fa[v * TN + threadIdx.x];
    if (threadIdx.x == 0) fabv = Fab[v];
    __syncthreads();
    for (int t = t0; t < t0 + 8; ++t) {
        const float* hr = &g_hsT[t][v * TN][0];
        float ap = fabv;
        #pragma unroll 8
        for (int n = 0; n < TN; ++n) ap += hr[n * TB + b] * fa[n];
        g_aunT[t][v][b] = expf(tanhf(ap));
    }
}

__global__ void k_alphaInv() {
    int v = blockIdx.x, b = threadIdx.x;
    float s = 0.f;
    for (int t = 0; t < TT; ++t) s += g_aunT[t][v][b];
    g_inv[v][b] = 1.f / s;
}

__global__ void k_gn() {
    int v = blockIdx.x, nc = blockIdx.y * 2, b = threadIdx.x;
    float a0 = 0.f, a1 = 0.f;
    for (int t = 0; t < TT; ++t) {
        float au = g_aunT[t][v][b];
        const float* hr = &g_hsT[t][v * TN + nc][0];
        a0 += au * hr[0 * TB + b];
        a1 += au * hr[1 * TB + b];
    }
    float inv = g_inv[v][b];
    g_gT[v * TN + nc + 0][b] = a0 * inv;
    g_gT[v * TN + nc + 1][b] = a1 * inv;
}

__global__ void k_alphaOut(float* __restrict__ out) {
    int t = blockIdx.x, b = threadIdx.x;
    float* ao = out + TB;
    #pragma unroll
    for (int v = 0; v < TV; ++v)
        ao[((size_t)b * TT + t) * TV + v] = g_aunT[t][v][b] * g_inv[v][b];
}

__global__ void k_final(const float* __restrict__ Fbw, const float* __restrict__ Fbb,
                        const float* __restrict__ Phw, const float* __restrict__ Phb,
                        float* __restrict__ out) {
    __shared__ float phi[2 * TN], fbw[2 * TN];
    __shared__ float phib, fbb;
    int b = threadIdx.x;
    if (threadIdx.x < 2 * TN) { phi[threadIdx.x] = Phw[threadIdx.x]; fbw[threadIdx.x] = Fbw[threadIdx.x]; }
    if (threadIdx.x == 0) { phib = Phb[0]; fbb = Fbb[0]; }
    __syncthreads();
    float mu[TV], bu[TV], bs = 0.f;
    #pragma unroll
    for (int v = 0; v < TV; ++v) {
        const float* gr = &g_gT[v * TN][0];
        const float* hr = &g_hsT[TT - 1][v * TN][0];
        float m_ = phib, p_ = fbb;
        #pragma unroll 8
        for (int n = 0; n < TN; ++n) {
            float gv = gr[n * TB + b], hv = hr[n * TB + b];
            m_ += gv * phi[n] + hv * phi[TN + n];
            p_ += gv * fbw[n] + hv * fbw[TN + n];
        }
        mu[v] = m_;
        float e = expf(tanhf(p_));
        bu[v] = e; bs += e;
    }
    float ib = 1.f / bs, mean = 0.f;
    float* bout = out + TB + (size_t)TB * TT * TV;
    #pragma unroll
    for (int v = 0; v < TV; ++v) {
        float be = bu[v] * ib;
        mean += be * mu[v];
        bout[(size_t)b * TV + v] = be;
    }
    out[b] = mean;
}

extern "C" void kernel_launch(void* const* d_in, const int* in_sizes, int n_in,
                              void* d_out, int out_size) {
    const float* x    = (const float*)d_in[0];
    const float* U_j  = (const float*)d_in[1];
    const float* W_j  = (const float*)d_in[2];
    const float* b_j  = (const float*)d_in[3];
    const float* Wi   = (const float*)d_in[4];
    const float* bi   = (const float*)d_in[5];
    const float* Wf   = (const float*)d_in[6];
    const float* bf   = (const float*)d_in[7];
    const float* Wo   = (const float*)d_in[8];
    const float* bo   = (const float*)d_in[9];
    const float* Fa   = (const float*)d_in[10];
    const float* Fab  = (const float*)d_in[11];
    const float* Fbw  = (const float*)d_in[12];
    const float* Fbb  = (const float*)d_in[13];
    const float* Phw  = (const float*)d_in[14];
    const float* Phb  = (const float*)d_in[15];
    float* out = (float*)d_out;

    static const int SMEM = 12288 * 4 + 24 * TB * 4;  // B-hi frags + D tile = 73728 B
    cudaFuncSetAttribute(k_recur, cudaFuncAttributeMaxDynamicSharedMemorySize, SMEM);

    k_xT<<<TT * TV, TB>>>(x);
    k_wfrag<<<dim3(384, 64), 64>>>(Wi, Wf, Wo);
    k_recur<<<NCTA, RTHREADS, SMEM>>>(U_j, W_j, b_j, Wi, bi, Wf, bf, Wo, bo);
    k_alphaA<<<dim3(TV, 25), TB>>>(Fa, Fab);
    k_alphaInv<<<TV, TB>>>();
    k_gn<<<dim3(TV, 32), TB>>>();
    k_alphaOut<<<TT, TB>>>(out);
    k_final<<<1, TB>>>(Fbw, Fbb, Phw, Phb, out);
}

// round 13
// speedup vs baseline: 2.1373x; 1.1888x over previous
#include <cuda_runtime.h>
#include <cuda_bf16.h>
#include <math.h>
#include <stdint.h>

#define TB 256
#define TT 200
#define TV 16
#define TN 64
#define TG 1024   // V*N
#define TK 1040   // V*(N+1)
#define NCTA 128
#define RTHREADS 256

__device__ float g_xT[TT][TV][TB];
__device__ float g_hsT[TT][TG][TB];
__device__ float g_aunT[TT][TV][TB];
__device__ float g_inv[TV][TB];
__device__ float g_gT[TG][TB];
__device__ __align__(16) uint32_t g_hA_hi[64 * 16 * 32 * 4];   // A fragments (h) bf16
__device__ __align__(16) uint32_t g_WB_hi[64 * 384 * 32 * 2];  // B fragments (W) bf16
__device__ unsigned g_bar;

__device__ __forceinline__ void mma_bf16(float* d, const uint32_t* a, const uint32_t* b) {
    asm volatile(
        "mma.sync.aligned.m16n8k16.row.col.f32.bf16.bf16.f32 "
        "{%0,%1,%2,%3}, {%4,%5,%6,%7}, {%8,%9}, {%0,%1,%2,%3};"
        : "+f"(d[0]), "+f"(d[1]), "+f"(d[2]), "+f"(d[3])
        : "r"(a[0]), "r"(a[1]), "r"(a[2]), "r"(a[3]), "r"(b[0]), "r"(b[1]));
}

__device__ __forceinline__ uint32_t pack_bf(float v0, float v1) {
    __nv_bfloat162 t = { __float2bfloat16(v0), __float2bfloat16(v1) };
    return *reinterpret_cast<uint32_t*>(&t);
}

__global__ void k_xT(const float* __restrict__ x) {
    int t = blockIdx.x >> 4, v = blockIdx.x & 15, b = threadIdx.x;
    g_xT[t][v][b] = x[(size_t)b * (TT * TV) + t * TV + v];
    if (blockIdx.x == 0 && threadIdx.x == 0) g_bar = 0u;
}

// precompute bf16 B fragments of gate weights (h-part cols 16..1039)
__global__ void k_wfrag(const float* __restrict__ Wi, const float* __restrict__ Wf,
                        const float* __restrict__ Wo) {
    int nt = blockIdx.x, kc = blockIdx.y;
    int l = threadIdx.x & 31, reg = threadIdx.x >> 5;
    int n = nt * 8 + (l >> 2);
    int gate = n >> 10, u = n & 1023;
    const float* W = (gate == 0) ? Wi : (gate == 1) ? Wf : Wo;
    int k0 = kc * 16 + (l & 3) * 2 + reg * 8;
    float v0 = W[(size_t)u * TK + 16 + k0];
    float v1 = W[(size_t)u * TK + 16 + k0 + 1];
    g_WB_hi[((size_t)(kc * 384 + nt) * 32 + l) * 2 + reg] = pack_bf(v0, v1);
}

__global__ void __launch_bounds__(RTHREADS, 1) k_recur(
    const float* __restrict__ U_j, const float* __restrict__ W_j, const float* __restrict__ b_j,
    const float* __restrict__ Wi, const float* __restrict__ bi,
    const float* __restrict__ Wf, const float* __restrict__ bf,
    const float* __restrict__ Wo, const float* __restrict__ bo)
{
    __shared__ float s_wgx[16 * 24];   // x-part weights [k][r], r = gate*8+ul
    __shared__ float s_wj[64 * 8];
    __shared__ float s_bg[24];
    __shared__ float s_bj[8];
    __shared__ float s_uu[8];
    extern __shared__ uint32_t smdyn[];
    uint32_t* s_Bh = smdyn;                     // [3][64][32][2] = 12288 u32
    float*    s_D  = (float*)(smdyn + 12288);   // [24][256]

    const int tid = threadIdx.x, cta = blockIdx.x;
    const int lane = tid & 31, wid = tid >> 5;
    const int g0 = cta * 8, v = g0 >> 6, n0 = g0 & 63;
    const int b = tid;

    // ---- one-time staging ----
    for (int e = tid; e < 16 * 24; e += RTHREADS) {
        int k = e / 24, r = e - k * 24, g = r >> 3, ul = r & 7;
        const float* W = (g == 0) ? Wi : (g == 1) ? Wf : Wo;
        s_wgx[e] = W[(size_t)(g0 + ul) * TK + k];
    }
    for (int e = tid; e < 512; e += RTHREADS)
        s_wj[e] = W_j[v * TN * TN + (e >> 3) * TN + (n0 + (e & 7))];
    if (tid < 24) {
        int g = tid >> 3, ul = tid & 7;
        s_bg[tid] = ((g == 0) ? bi : (g == 1) ? bf : bo)[g0 + ul];
    }
    if (tid < 8) { s_bj[tid] = b_j[v * TN + n0 + tid]; s_uu[tid] = U_j[v * TN + n0 + tid]; }
    // B fragments for this CTA's 24 N-rows: nt = g*128 + cta
    for (int e = tid; e < 12288; e += RTHREADS) {
        int reg = e & 1, l = (e >> 1) & 31, kc = (e >> 6) & 63, g = e >> 12;
        s_Bh[e] = g_WB_hi[((size_t)(kc * 384 + g * 128 + cta) * 32 + l) * 2 + reg];
    }
    __syncthreads();

    // epilogue A-fragment write constants (thread = batch column b)
    const int kc_e = g0 >> 4;
    const int mt_e = b >> 4, r_e = b & 15;
    const int reg_e = ((r_e >> 3) & 1) | ((g0 & 8) ? 2 : 0);
    const int lane_e = (r_e & 7) * 4;

    float cc[8];
    #pragma unroll
    for (int u = 0; u < 8; ++u) cc[u] = 0.f;

    for (int t = 0; t < TT; ++t) {
        // ========== GEMM: 24 N-rows x 256 batch, K=1024, pure bf16 ==========
        if (t > 0) {
            float acc[2][3][4];
            #pragma unroll
            for (int i = 0; i < 2; ++i)
                #pragma unroll
                for (int g = 0; g < 3; ++g)
                    #pragma unroll
                    for (int q = 0; q < 4; ++q) acc[i][g][q] = 0.f;

            const uint4* __restrict__ Ah = (const uint4*)g_hA_hi;
            const int mt0 = wid * 2, mt1 = mt0 + 1;

            uint4 ah0 = Ah[(0 * 16 + mt0) * 32 + lane];
            uint4 ah1 = Ah[(0 * 16 + mt1) * 32 + lane];

            #pragma unroll 4
            for (int kc = 0; kc < 64; ++kc) {
                uint4 nah0, nah1;
                if (kc < 63) {
                    int kn = kc + 1;
                    nah0 = Ah[(kn * 16 + mt0) * 32 + lane];
                    nah1 = Ah[(kn * 16 + mt1) * 32 + lane];
                }
                #pragma unroll
                for (int g = 0; g < 3; ++g) {
                    uint2 bh = *(const uint2*)&s_Bh[((g * 64 + kc) * 32 + lane) * 2];
                    mma_bf16(acc[0][g], (const uint32_t*)&ah0, (const uint32_t*)&bh);
                    mma_bf16(acc[1][g], (const uint32_t*)&ah1, (const uint32_t*)&bh);
                }
                if (kc < 63) { ah0 = nah0; ah1 = nah1; }
            }
            // D -> smem transpose tile [n=24][batch=256]
            #pragma unroll
            for (int i = 0; i < 2; ++i) {
                int mbase = (wid * 2 + i) * 16 + (lane >> 2);
                #pragma unroll
                for (int g = 0; g < 3; ++g) {
                    int n = g * 8 + (lane & 3) * 2;
                    s_D[n * TB + mbase]           = acc[i][g][0];
                    s_D[(n + 1) * TB + mbase]     = acc[i][g][1];
                    s_D[n * TB + mbase + 8]       = acc[i][g][2];
                    s_D[(n + 1) * TB + mbase + 8] = acc[i][g][3];
                }
            }
        }
        __syncthreads();

        // ========== epilogue (thread = batch b) ==========
        {
            float zz[24];
            #pragma unroll
            for (int r = 0; r < 24; ++r)
                zz[r] = s_bg[r] + ((t > 0) ? s_D[r * TB + b] : 0.f);
            const float* xt = &g_xT[t][0][0];
            #pragma unroll
            for (int k = 0; k < TV; ++k) {
                float xv = xt[k * TB + b];
                const float* wr = s_wgx + k * 24;
                #pragma unroll
                for (int r = 0; r < 24; ++r) zz[r] += xv * wr[r];
            }
            float xvo = xt[v * TB + b];
            float jac[8];
            #pragma unroll
            for (int u = 0; u < 8; ++u) jac[u] = s_bj[u] + xvo * s_uu[u];
            if (t > 0) {
                const float* hv = &g_hsT[t - 1][v * TN][0];
                #pragma unroll 8
                for (int m = 0; m < TN; ++m) {
                    float hm = hv[m * TB + b];
                    const float* wr = s_wj + m * 8;
                    #pragma unroll
                    for (int u = 0; u < 8; ++u) jac[u] += hm * wr[u];
                }
            }
            float hval[8];
            float* ho = &g_hsT[t][0][0];
            #pragma unroll
            for (int ul = 0; ul < 8; ++ul) {
                float iv = 1.f / (1.f + expf(-zz[ul]));
                float fv = 1.f / (1.f + expf(-zz[8 + ul]));
                float ov = 1.f / (1.f + expf(-zz[16 + ul]));
                float jv = tanhf(jac[ul]);
                float cn = cc[ul] * fv + iv * jv;
                cc[ul] = cn;
                hval[ul] = ov * tanhf(cn);
                ho[(size_t)(g0 + ul) * TB + b] = hval[ul];
            }
            #pragma unroll
            for (int p = 0; p < 4; ++p) {
                size_t idx = ((size_t)(kc_e * 16 + mt_e) * 32 + lane_e + p) * 4 + reg_e;
                g_hA_hi[idx] = pack_bf(hval[2 * p], hval[2 * p + 1]);
            }
        }

        // single grid barrier per step (h + fragments ready)
        __syncthreads();
        if (tid == 0) {
            __threadfence(); atomicAdd(&g_bar, 1u);
            unsigned target = (unsigned)(t + 1) * NCTA;
            while (*((volatile unsigned*)&g_bar) < target) { }
            __threadfence();
        }
        __syncthreads();
    }
}

__global__ void k_alphaA(const float* __restrict__ Fa, const float* __restrict__ Fab) {
    __shared__ float fa[TN]; __shared__ float fabv;
    int v = blockIdx.x, t0 = blockIdx.y * 8, b = threadIdx.x;
    if (threadIdx.x < TN) fa[threadIdx.x] = Fa[v * TN + threadIdx.x];
    if (threadIdx.x == 0) fabv = Fab[v];
    __syncthreads();
    for (int t = t0; t < t0 + 8; ++t) {
        const float* hr = &g_hsT[t][v * TN][0];
        float ap = fabv;
        #pragma unroll 8
        for (int n = 0; n < TN; ++n) ap += hr[n * TB + b] * fa[n];
        g_aunT[t][v][b] = expf(tanhf(ap));
    }
}

__global__ void k_alphaInv() {
    int v = blockIdx.x, b = threadIdx.x;
    float s = 0.f;
    for (int t = 0; t < TT; ++t) s += g_aunT[t][v][b];
    g_inv[v][b] = 1.f / s;
}

__global__ void k_gn() {
    int v = blockIdx.x, nc = blockIdx.y * 2, b = threadIdx.x;
    float a0 = 0.f, a1 = 0.f;
    for (int t = 0; t < TT; ++t) {
        float au = g_aunT[t][v][b];
        const float* hr = &g_hsT[t][v * TN + nc][0];
        a0 += au * hr[0 * TB + b];
        a1 += au * hr[1 * TB + b];
    }
    float inv = g_inv[v][b];
    g_gT[v * TN + nc + 0][b] = a0 * inv;
    g_gT[v * TN + nc + 1][b] = a1 * inv;
}

__global__ void k_alphaOut(float* __restrict__ out) {
    int t = blockIdx.x, b = threadIdx.x;
    float* ao = out + TB;
    #pragma unroll
    for (int v = 0; v < TV; ++v)
        ao[((size_t)b * TT + t) * TV + v] = g_aunT[t][v][b] * g_inv[v][b];
}

__global__ void k_final(const float* __restrict__ Fbw, const float* __restrict__ Fbb,
                        const float* __restrict__ Phw, const float* __restrict__ Phb,
                        float* __restrict__ out) {
    __shared__ float phi[2 * TN], fbw[2 * TN];
    __shared__ float phib, fbb;
    int b = threadIdx.x;
    if (threadIdx.x < 2 * TN) { phi[threadIdx.x] = Phw[threadIdx.x]; fbw[threadIdx.x] = Fbw[threadIdx.x]; }
    if (threadIdx.x == 0) { phib = Phb[0]; fbb = Fbb[0]; }
    __syncthreads();
    float mu[TV], bu[TV], bs = 0.f;
    #pragma unroll
    for (int v = 0; v < TV; ++v) {
        const float* gr = &g_gT[v * TN][0];
        const float* hr = &g_hsT[TT - 1][v * TN][0];
        float m_ = phib, p_ = fbb;
        #pragma unroll 8
        for (int n = 0; n < TN; ++n) {
            float gv = gr[n * TB + b], hv = hr[n * TB + b];
            m_ += gv * phi[n] + hv * phi[TN + n];
            p_ += gv * fbw[n] + hv * fbw[TN + n];
        }
        mu[v] = m_;
        float e = expf(tanhf(p_));
        bu[v] = e; bs += e;
    }
    float ib = 1.f / bs, mean = 0.f;
    float* bout = out + TB + (size_t)TB * TT * TV;
    #pragma unroll
    for (int v = 0; v < TV; ++v) {
        float be = bu[v] * ib;
        mean += be * mu[v];
        bout[(size_t)b * TV + v] = be;
    }
    out[b] = mean;
}

extern "C" void kernel_launch(void* const* d_in, const int* in_sizes, int n_in,
                              void* d_out, int out_size) {
    const float* x    = (const float*)d_in[0];
    const float* U_j  = (const float*)d_in[1];
    const float* W_j  = (const float*)d_in[2];
    const float* b_j  = (const float*)d_in[3];
    const float* Wi   = (const float*)d_in[4];
    const float* bi   = (const float*)d_in[5];
    const float* Wf   = (const float*)d_in[6];
    const float* bf   = (const float*)d_in[7];
    const float* Wo   = (const float*)d_in[8];
    const float* bo   = (const float*)d_in[9];
    const float* Fa   = (const float*)d_in[10];
    const float* Fab  = (const float*)d_in[11];
    const float* Fbw  = (const float*)d_in[12];
    const float* Fbb  = (const float*)d_in[13];
    const float* Phw  = (const float*)d_in[14];
    const float* Phb  = (const float*)d_in[15];
    float* out = (float*)d_out;

    static const int SMEM = 12288 * 4 + 24 * TB * 4;  // B frags + D tile = 73728 B
    cudaFuncSetAttribute(k_recur, cudaFuncAttributeMaxDynamicSharedMemorySize, SMEM);

    k_xT<<<TT * TV, TB>>>(x);
    k_wfrag<<<dim3(384, 64), 64>>>(Wi, Wf, Wo);
    k_recur<<<NCTA, RTHREADS, SMEM>>>(U_j, W_j, b_j, Wi, bi, Wf, bf, Wo, bo);
    k_alphaA<<<dim3(TV, 25), TB>>>(Fa, Fab);
    k_alphaInv<<<TV, TB>>>();
    k_gn<<<dim3(TV, 32), TB>>>();
    k_alphaOut<<<TT, TB>>>(out);
    k_final<<<1, TB>>>(Fbw, Fbb, Phw, Phb, out);
}

// round 15
// speedup vs baseline: 2.8678x; 1.3418x over previous
#include <cuda_runtime.h>
#include <cuda_bf16.h>
#include <math.h>
#include <stdint.h>

#define TB 256
#define TT 200
#define TV 16
#define TN 64
#define TG 1024   // V*N
#define TK 1040   // V*(N+1)
#define NCTA 128
#define RTHREADS 256

__device__ float g_xT[TT][TV][TB];
__device__ float g_hsT[TT][TG][TB];
__device__ float g_aunT[TT][TV][TB];
__device__ float g_inv[TV][TB];
__device__ float g_gT[TG][TB];
__device__ __align__(16) uint32_t g_hA_hi[64 * 16 * 32 * 4];   // A fragments (h) bf16
__device__ __align__(16) uint32_t g_WB_hi[64 * 384 * 32 * 2];  // B fragments (W) bf16
__device__ unsigned g_bar;

__device__ __forceinline__ void mma_bf16(float* d, const uint32_t* a, const uint32_t* b) {
    asm volatile(
        "mma.sync.aligned.m16n8k16.row.col.f32.bf16.bf16.f32 "
        "{%0,%1,%2,%3}, {%4,%5,%6,%7}, {%8,%9}, {%0,%1,%2,%3};"
        : "+f"(d[0]), "+f"(d[1]), "+f"(d[2]), "+f"(d[3])
        : "r"(a[0]), "r"(a[1]), "r"(a[2]), "r"(a[3]), "r"(b[0]), "r"(b[1]));
}

__device__ __forceinline__ uint32_t pack_bf(float v0, float v1) {
    __nv_bfloat162 t = { __float2bfloat16(v0), __float2bfloat16(v1) };
    return *reinterpret_cast<uint32_t*>(&t);
}

__global__ void k_xT(const float* __restrict__ x) {
    int t = blockIdx.x >> 4, v = blockIdx.x & 15, b = threadIdx.x;
    g_xT[t][v][b] = x[(size_t)b * (TT * TV) + t * TV + v];
    if (blockIdx.x == 0 && threadIdx.x == 0) g_bar = 0u;
}

// precompute bf16 B fragments of gate weights (h-part cols 16..1039)
__global__ void k_wfrag(const float* __restrict__ Wi, const float* __restrict__ Wf,
                        const float* __restrict__ Wo) {
    int nt = blockIdx.x, kc = blockIdx.y;
    int l = threadIdx.x & 31, reg = threadIdx.x >> 5;
    int n = nt * 8 + (l >> 2);
    int gate = n >> 10, u = n & 1023;
    const float* W = (gate == 0) ? Wi : (gate == 1) ? Wf : Wo;
    int k0 = kc * 16 + (l & 3) * 2 + reg * 8;
    float v0 = W[(size_t)u * TK + 16 + k0];
    float v1 = W[(size_t)u * TK + 16 + k0 + 1];
    g_WB_hi[((size_t)(kc * 384 + nt) * 32 + l) * 2 + reg] = pack_bf(v0, v1);
}

__global__ void __launch_bounds__(RTHREADS, 1) k_recur(
    const float* __restrict__ U_j, const float* __restrict__ W_j, const float* __restrict__ b_j,
    const float* __restrict__ Wi, const float* __restrict__ bi,
    const float* __restrict__ Wf, const float* __restrict__ bf,
    const float* __restrict__ Wo, const float* __restrict__ bo)
{
    __shared__ float s_wgx[16 * 48];   // x-part weights [k][r], r = g*16+u
    __shared__ float s_bg[48];
    __shared__ float s_bj[16];
    __shared__ float s_uu[16];
    extern __shared__ uint32_t smdyn[];
    uint32_t* s_Bh = smdyn;                     // [6 gj][64 kc][32 l][2 reg] = 24576 u32
    uint32_t* s_Bj = smdyn + 24576;             // [2 jt][4 kk][32 l][2 reg] = 512 u32
    float*    s_D  = (float*)(smdyn + 25088);   // [64 n][128 m] (rows 48..63 = j)

    const int tid = threadIdx.x, cta = blockIdx.x;
    const int lane = tid & 31, wid = tid >> 5;
    const int mh = cta & 1, ng = cta >> 1;
    const int g0 = ng * 16, v = g0 >> 6, n0 = g0 & 63;
    const int bl = tid & 127, uh = tid >> 7;
    const int bg = mh * 128 + bl;               // global batch column

    // ---- one-time staging ----
    for (int e = tid; e < 16 * 48; e += RTHREADS) {
        int k = e / 48, r = e - k * 48, g = r >> 4, u = r & 15;
        const float* W = (g == 0) ? Wi : (g == 1) ? Wf : Wo;
        s_wgx[e] = W[(size_t)(g0 + u) * TK + k];
    }
    if (tid < 48) {
        int g = tid >> 4, u = tid & 15;
        s_bg[tid] = ((g == 0) ? bi : (g == 1) ? bf : bo)[g0 + u];
    }
    if (tid < 16) { s_bj[tid] = b_j[v * TN + n0 + tid]; s_uu[tid] = U_j[v * TN + n0 + tid]; }
    // gate B fragments: nt = g*128 + ng*2 + j
    for (int e = tid; e < 24576; e += RTHREADS) {
        int reg = e & 1, l = (e >> 1) & 31, kc = (e >> 6) & 63, gj = e >> 12;
        int g = gj >> 1, j = gj & 1;
        s_Bh[e] = g_WB_hi[((size_t)(kc * 384 + g * 128 + ng * 2 + j) * 32 + l) * 2 + reg];
    }
    // j B fragments (FIX: loop, not single pass — 512 entries, 256 threads)
    for (int e = tid; e < 512; e += RTHREADS) {
        int reg = e & 1, l = (e >> 1) & 31, kk = (e >> 6) & 3, jt = e >> 8;
        int n = jt * 8 + (l >> 2);
        int k0 = kk * 16 + (l & 3) * 2 + reg * 8;
        float v0 = W_j[v * TN * TN + k0 * TN + (n0 + n)];
        float v1 = W_j[v * TN * TN + (k0 + 1) * TN + (n0 + n)];
        s_Bj[e] = pack_bf(v0, v1);
    }
    __syncthreads();

    // epilogue A-fragment write constants (thread = batch column bg)
    const int mt_e = bg >> 4, r_e = bg & 15;
    const int reg_e = ((r_e >> 3) & 1) | (uh << 1);
    const int lane_e = (r_e & 7) * 4;

    float cc[8];
    #pragma unroll
    for (int u = 0; u < 8; ++u) cc[u] = 0.f;

    for (int t = 0; t < TT; ++t) {
        // ========== GEMM: M=128 (this batch half) x N=48 gates + N=16 j ==========
        if (t > 0) {
            float acc[6][4];
            #pragma unroll
            for (int gj = 0; gj < 6; ++gj)
                #pragma unroll
                for (int q = 0; q < 4; ++q) acc[gj][q] = 0.f;

            const uint4* __restrict__ Ah = (const uint4*)g_hA_hi;
            const int mt = mh * 8 + wid;

            uint4 ah = Ah[(0 * 16 + mt) * 32 + lane];
            #pragma unroll 4
            for (int kc = 0; kc < 64; ++kc) {
                uint4 nah;
                if (kc < 63) nah = Ah[((kc + 1) * 16 + mt) * 32 + lane];
                #pragma unroll
                for (int gj = 0; gj < 6; ++gj) {
                    uint2 bh = *(const uint2*)&s_Bh[(gj * 64 + kc) * 64 + lane * 2];
                    mma_bf16(acc[gj], (const uint32_t*)&ah, (const uint32_t*)&bh);
                }
                if (kc < 63) ah = nah;
            }
            // block-diagonal j: kc = v*4 .. v*4+3, 2 n-tiles of 8
            float accj[2][4];
            #pragma unroll
            for (int jt = 0; jt < 2; ++jt)
                #pragma unroll
                for (int q = 0; q < 4; ++q) accj[jt][q] = 0.f;
            #pragma unroll
            for (int kk = 0; kk < 4; ++kk) {
                uint4 aj = Ah[((v * 4 + kk) * 16 + mt) * 32 + lane];
                #pragma unroll
                for (int jt = 0; jt < 2; ++jt) {
                    uint2 bj = *(const uint2*)&s_Bj[((jt * 4 + kk) * 32 + lane) * 2];
                    mma_bf16(accj[jt], (const uint32_t*)&aj, (const uint32_t*)&bj);
                }
            }
            // D -> smem transpose tile [n][m=128]
            int m = wid * 16 + (lane >> 2);
            #pragma unroll
            for (int gj = 0; gj < 6; ++gj) {
                int n = (gj >> 1) * 16 + (gj & 1) * 8 + (lane & 3) * 2;
                s_D[n * 128 + m]           = acc[gj][0];
                s_D[(n + 1) * 128 + m]     = acc[gj][1];
                s_D[n * 128 + m + 8]       = acc[gj][2];
                s_D[(n + 1) * 128 + m + 8] = acc[gj][3];
            }
            #pragma unroll
            for (int jt = 0; jt < 2; ++jt) {
                int n = 48 + jt * 8 + (lane & 3) * 2;
                s_D[n * 128 + m]           = accj[jt][0];
                s_D[(n + 1) * 128 + m]     = accj[jt][1];
                s_D[n * 128 + m + 8]       = accj[jt][2];
                s_D[(n + 1) * 128 + m + 8] = accj[jt][3];
            }
        }
        __syncthreads();

        // ========== epilogue (thread = batch bg, units g0+uh*8 .. +7) ==========
        {
            float zz[24];
            #pragma unroll
            for (int g = 0; g < 3; ++g)
                #pragma unroll
                for (int ul = 0; ul < 8; ++ul) {
                    int r = g * 16 + uh * 8 + ul;
                    zz[g * 8 + ul] = s_bg[r] + ((t > 0) ? s_D[r * 128 + bl] : 0.f);
                }
            const float* xt = &g_xT[t][0][0];
            #pragma unroll
            for (int k = 0; k < TV; ++k) {
                float xv = xt[k * TB + bg];
                const float* wr = s_wgx + k * 48 + uh * 8;
                #pragma unroll
                for (int g = 0; g < 3; ++g)
                    #pragma unroll
                    for (int ul = 0; ul < 8; ++ul)
                        zz[g * 8 + ul] += xv * wr[g * 16 + ul];
            }
            float xvo = xt[v * TB + bg];
            float hval[8];
            float* ho = &g_hsT[t][0][0];
            #pragma unroll
            for (int ul = 0; ul < 8; ++ul) {
                float jz = s_bj[uh * 8 + ul] + xvo * s_uu[uh * 8 + ul];
                if (t > 0) jz += s_D[(48 + uh * 8 + ul) * 128 + bl];
                float iv = 1.f / (1.f + expf(-zz[ul]));
                float fv = 1.f / (1.f + expf(-zz[8 + ul]));
                float ov = 1.f / (1.f + expf(-zz[16 + ul]));
                float jv = tanhf(jz);
                float cn = cc[ul] * fv + iv * jv;
                cc[ul] = cn;
                hval[ul] = ov * tanhf(cn);
                ho[(size_t)(g0 + uh * 8 + ul) * TB + bg] = hval[ul];
            }
            #pragma unroll
            for (int p = 0; p < 4; ++p) {
                size_t idx = ((size_t)(ng * 16 + mt_e) * 32 + lane_e + p) * 4 + reg_e;
                g_hA_hi[idx] = pack_bf(hval[2 * p], hval[2 * p + 1]);
            }
        }

        // single grid barrier per step (h + fragments ready)
        __syncthreads();
        if (tid == 0) {
            __threadfence(); atomicAdd(&g_bar, 1u);
            unsigned target = (unsigned)(t + 1) * NCTA;
            while (*((volatile unsigned*)&g_bar) < target) { }
            __threadfence();
        }
        __syncthreads();
    }
}

__global__ void k_alphaA(const float* __restrict__ Fa, const float* __restrict__ Fab) {
    __shared__ float fa[TN]; __shared__ float fabv;
    int v = blockIdx.x, t0 = blockIdx.y * 8, b = threadIdx.x;
    if (threadIdx.x < TN) fa[threadIdx.x] = Fa[v * TN + threadIdx.x];
    if (threadIdx.x == 0) fabv = Fab[v];
    __syncthreads();
    for (int t = t0; t < t0 + 8; ++t) {
        const float* hr = &g_hsT[t][v * TN][0];
        float ap = fabv;
        #pragma unroll 8
        for (int n = 0; n < TN; ++n) ap += hr[n * TB + b] * fa[n];
        g_aunT[t][v][b] = expf(tanhf(ap));
    }
}

__global__ void k_alphaInv() {
    int v = blockIdx.x, b = threadIdx.x;
    float s = 0.f;
    for (int t = 0; t < TT; ++t) s += g_aunT[t][v][b];
    g_inv[v][b] = 1.f / s;
}

__global__ void k_gn() {
    int v = blockIdx.x, nc = blockIdx.y * 2, b = threadIdx.x;
    float a0 = 0.f, a1 = 0.f;
    for (int t = 0; t < TT; ++t) {
        float au = g_aunT[t][v][b];
        const float* hr = &g_hsT[t][v * TN + nc][0];
        a0 += au * hr[0 * TB + b];
        a1 += au * hr[1 * TB + b];
    }
    float inv = g_inv[v][b];
    g_gT[v * TN + nc + 0][b] = a0 * inv;
    g_gT[v * TN + nc + 1][b] = a1 * inv;
}

__global__ void k_alphaOut(float* __restrict__ out) {
    int t = blockIdx.x, b = threadIdx.x;
    float* ao = out + TB;
    #pragma unroll
    for (int v = 0; v < TV; ++v)
        ao[((size_t)b * TT + t) * TV + v] = g_aunT[t][v][b] * g_inv[v][b];
}

__global__ void k_final(const float* __restrict__ Fbw, const float* __restrict__ Fbb,
                        const float* __restrict__ Phw, const float* __restrict__ Phb,
                        float* __restrict__ out) {
    __shared__ float phi[2 * TN], fbw[2 * TN];
    __shared__ float phib, fbb;
    int b = threadIdx.x;
    if (threadIdx.x < 2 * TN) { phi[threadIdx.x] = Phw[threadIdx.x]; fbw[threadIdx.x] = Fbw[threadIdx.x]; }
    if (threadIdx.x == 0) { phib = Phb[0]; fbb = Fbb[0]; }
    __syncthreads();
    float mu[TV], bu[TV], bs = 0.f;
    #pragma unroll
    for (int v = 0; v < TV; ++v) {
        const float* gr = &g_gT[v * TN][0];
        const float* hr = &g_hsT[TT - 1][v * TN][0];
        float m_ = phib, p_ = fbb;
        #pragma unroll 8
        for (int n = 0; n < TN; ++n) {
            float gv = gr[n * TB + b], hv = hr[n * TB + b];
            m_ += gv * phi[n] + hv * phi[TN + n];
            p_ += gv * fbw[n] + hv * fbw[TN + n];
        }
        mu[v] = m_;
        float e = expf(tanhf(p_));
        bu[v] = e; bs += e;
    }
    float ib = 1.f / bs, mean = 0.f;
    float* bout = out + TB + (size_t)TB * TT * TV;
    #pragma unroll
    for (int v = 0; v < TV; ++v) {
        float be = bu[v] * ib;
        mean += be * mu[v];
        bout[(size_t)b * TV + v] = be;
    }
    out[b] = mean;
}

extern "C" void kernel_launch(void* const* d_in, const int* in_sizes, int n_in,
                              void* d_out, int out_size) {
    const float* x    = (const float*)d_in[0];
    const float* U_j  = (const float*)d_in[1];
    const float* W_j  = (const float*)d_in[2];
    const float* b_j  = (const float*)d_in[3];
    const float* Wi   = (const float*)d_in[4];
    const float* bi   = (const float*)d_in[5];
    const float* Wf   = (const float*)d_in[6];
    const float* bf   = (const float*)d_in[7];
    const float* Wo   = (const float*)d_in[8];
    const float* bo   = (const float*)d_in[9];
    const float* Fa   = (const float*)d_in[10];
    const float* Fab  = (const float*)d_in[11];
    const float* Fbw  = (const float*)d_in[12];
    const float* Fbb  = (const float*)d_in[13];
    const float* Phw  = (const float*)d_in[14];
    const float* Phb  = (const float*)d_in[15];
    float* out = (float*)d_out;

    static const int SMEM = 24576 * 4 + 512 * 4 + 64 * 128 * 4;  // 133120 B
    cudaFuncSetAttribute(k_recur, cudaFuncAttributeMaxDynamicSharedMemorySize, SMEM);

    k_xT<<<TT * TV, TB>>>(x);
    k_wfrag<<<dim3(384, 64), 64>>>(Wi, Wf, Wo);
    k_recur<<<NCTA, RTHREADS, SMEM>>>(U_j, W_j, b_j, Wi, bi, Wf, bf, Wo, bo);
    k_alphaA<<<dim3(TV, 25), TB>>>(Fa, Fab);
    k_alphaInv<<<TV, TB>>>();
    k_gn<<<dim3(TV, 32), TB>>>();
    k_alphaOut<<<TT, TB>>>(out);
    k_final<<<1, TB>>>(Fbw, Fbb, Phw, Phb, out);
}